// round 14
// baseline (speedup 1.0000x reference)
#include <cuda_runtime.h>

#define KK     3
#define CIN    16
#define COUT   16
#define HH     64
#define WW     64
#define BB     4

#define TILE_H 16         // output rows per block
#define TX     32         // threads in x: each covers 2 output cols
#define TY     4          // threads in y: each covers 4 output rows
#define PXR    4          // pixel rows per thread
#define PXC    2          // pixel cols per thread
#define FG     2          // output channels per block (1 packed f32x2 pair)
#define CQ     2          // input channels per block (CIN split in 8)

#define SX_ROWS (TILE_H + 2)                 // 18
#define NOUT    (BB * COUT * HH * WW)        // 1,048,576

typedef unsigned long long ull;

// ---------------- Blackwell packed f32x2 helpers ----------------
__device__ __forceinline__ ull pk2s(float v) {            // (v, v)
    ull r; asm("mov.b64 %0, {%1, %1};" : "=l"(r) : "f"(v)); return r;
}
__device__ __forceinline__ void upk2(ull v, float& lo, float& hi) {
    asm("mov.b64 {%0, %1}, %2;" : "=f"(lo), "=f"(hi) : "l"(v));
}
__device__ __forceinline__ ull pk2(float lo, float hi) {
    ull r; asm("mov.b64 %0, {%1, %2};" : "=l"(r) : "f"(lo), "f"(hi)); return r;
}
__device__ __forceinline__ ull ffma2(ull a, ull b, ull c) {
    ull d; asm("fma.rn.f32x2 %0, %1, %2, %3;" : "=l"(d) : "l"(a), "l"(b), "l"(c)); return d;
}
__device__ __forceinline__ ull fmul2(ull a, ull b) {
    ull d; asm("mul.rn.f32x2 %0, %1, %2;" : "=l"(d) : "l"(a), "l"(b)); return d;
}
__device__ __forceinline__ float frcp(float x) {
    float r; asm("rcp.approx.ftz.f32 %0, %1;" : "=f"(r) : "f"(x)); return r;
}
__device__ __forceinline__ void redg_add(float* p, float v) {
    asm volatile("red.global.add.f32 [%0], %1;" :: "l"(p), "f"(v) : "memory");
}

// ---- zero the output buffer (poisoned by harness) ----
__global__ __launch_bounds__(128)
void zero_kernel(float* __restrict__ out) {
    const int i = blockIdx.x * 128 + threadIdx.x;       // float4 index
    reinterpret_cast<float4*>(out)[i] = make_float4(0.f, 0.f, 0.f, 0.f);
}

// Static SMEM (~10.8 KB):
//  sC: packed coefficients, this block's f-pair x its 2 input channels:
//      per (c,p): 10 float2 (6 A-pairs, 4 B-pairs) -> 180 float2 = 1440 B
//  sX: 2 input-channel tiles, 18 rows x 66 cols = 9504 B
__global__ __launch_bounds__(TX * TY, 6)    // 85-reg budget, 6 blocks/SM
void kaconv_kernel(const float* __restrict__ x,
                   const float* __restrict__ A,
                   const float* __restrict__ Bc,
                   float* __restrict__ out) {
    __shared__ __align__(16) ull  sC[CQ * 9 * 10];   // 180 slots = 1440 B
    __shared__ float              sX[CQ * SX_ROWS * 66];

    const int tx  = threadIdx.x;                     // 0..31 (col-pair)
    const int ty  = threadIdx.y;                     // 0..3  (row-quad)
    const int tid = ty * TX + tx;
    const int h0  = blockIdx.x * TILE_H;
    const int b   = blockIdx.y;
    const int f0  = (blockIdx.z >> 3) * FG;
    const int ce  = blockIdx.z & 7;            // which c-eighth
    const int c0  = ce * CQ;

    // ---- stage packed coefficients for channels c0, c0+1 ----
    float2* sCf = reinterpret_cast<float2*>(sC);
    for (int i = tid; i < CQ * 9 * 10; i += TX * TY) {
        int ii = i;
        const int k = ii % 10; ii /= 10;
        const int p = ii % 9;
        const int c = c0 + ii / 9;
        float lo, hi;
        if (k < 6) {
            lo = A[(( f0      * CIN + c) * 9 + p) * 6 + k];
            hi = A[(((f0 + 1) * CIN + c) * 9 + p) * 6 + k];
        } else {
            const int j = k - 6;
            lo = Bc[(( f0      * CIN + c) * 9 + p) * 4 + j];
            hi = Bc[(((f0 + 1) * CIN + c) * 9 + p) * 4 + j];
        }
        sCf[i] = make_float2(lo, hi);
    }

    // ---- stage 2 input-channel tiles with zero-padded halo ----
    for (int i = tid; i < CQ * SX_ROWS * 66; i += TX * TY) {
        const int col = i % 66;
        const int r   = (i / 66) % SX_ROWS;
        const int cl  = i / (66 * SX_ROWS);
        const int gh  = h0 + r - 1;
        const int gw  = col - 1;
        float v = 0.0f;
        if (gh >= 0 && gh < HH && gw >= 0 && gw < WW)
            v = x[((b * CIN + c0 + cl) * HH + gh) * WW + gw];
        sX[(cl * SX_ROWS + r) * 66 + col] = v;
    }
    __syncthreads();

    const ulonglong2* sC2 = reinterpret_cast<const ulonglong2*>(sC);
    // thread's x-window base: rows 4*ty.., cols 2*tx.. (halo-shifted)
    const float* xbase = sX + (PXR * ty) * 66 + PXC * tx;

    ull acc[PXR][PXC];
    #pragma unroll
    for (int i = 0; i < PXR; i++)
        #pragma unroll
        for (int j = 0; j < PXC; j++) acc[i][j] = 0ull;

    #pragma unroll 1
    for (int c = 0; c < CQ; c++) {
        // 6 rows x 4 cols register window covers all 8 pixels' 3x3 windows
        float xr[PXR + 2][PXC + 2];
        #pragma unroll
        for (int r = 0; r < PXR + 2; r++)
            #pragma unroll
            for (int j = 0; j < PXC + 2; j++)
                xr[r][j] = xbase[(c * SX_ROWS + r) * 66 + j];

        const ulonglong2* pc = sC2 + c * 45;   // 5 ulonglong2 per (c,p)
        #pragma unroll
        for (int p = 0; p < 9; p++) {
            const int di = p / 3, dj = p % 3;
            const ulonglong2 u0 = pc[p * 5 + 0];  // {A0, A1}
            const ulonglong2 u1 = pc[p * 5 + 1];  // {A2, A3}
            const ulonglong2 u2 = pc[p * 5 + 2];  // {A4, A5}
            const ulonglong2 u3 = pc[p * 5 + 3];  // {B1, B2}
            const ulonglong2 u4 = pc[p * 5 + 4];  // {B3, B4}

            #pragma unroll
            for (int py = 0; py < PXR; py++) {
                #pragma unroll
                for (int cc = 0; cc < PXC; cc++) {
                    const ull X = pk2s(xr[py + di][cc + dj]);

                    // P = a0 + ... + a5 x^5 (Horner, packed over f-pair)
                    ull P = ffma2(u2.y, X, u2.x);
                    P = ffma2(P, X, u1.y);
                    P = ffma2(P, X, u1.x);
                    P = ffma2(P, X, u0.y);
                    P = ffma2(P, X, u0.x);

                    // S = x*(b1 + x*(b2 + x*(b3 + x*b4)))
                    ull T = ffma2(u4.y, X, u4.x);
                    T = ffma2(T, X, u3.y);
                    T = ffma2(T, X, u3.x);
                    T = fmul2(T, X);

                    // Q = 1 + |S| (abs free on FADD); R = 1/Q via MUFU
                    float t0, t1; upk2(T, t0, t1);
                    const ull R = pk2(frcp(1.0f + fabsf(t0)),
                                      frcp(1.0f + fabsf(t1)));

                    acc[py][cc] = ffma2(P, R, acc[py][cc]);
                }
            }
        }
    }

    // ---- accumulate into out via fire-and-forget global reductions ----
    // out starts at 0; eight contributions per element (one per c-eighth).
    const int hA = h0 + PXR * ty;
    const int w0 = PXC * tx;
    float* op = out + ((b * COUT + f0) * HH + hA) * WW + w0;
    #pragma unroll
    for (int py = 0; py < PXR; py++) {
        #pragma unroll
        for (int cc = 0; cc < PXC; cc++) {
            float lo, hi;
            upk2(acc[py][cc], lo, hi);
            redg_add(op + py * WW + cc,           lo);
            redg_add(op + HH * WW + py * WW + cc, hi);
        }
    }
}

extern "C" void kernel_launch(void* const* d_in, const int* in_sizes, int n_in,
                              void* d_out, int out_size) {
    const float* x  = (const float*)d_in[0];
    const float* A  = (const float*)d_in[1];
    const float* Bc = (const float*)d_in[2];
    float* out = (float*)d_out;

    zero_kernel<<<(NOUT / 4) / 128, 128>>>(out);    // 2048 blocks, 4 MB zeros

    // (64/16, 4, 8 f-pairs * 8 c-eighths) = (4, 4, 64) = 1024 blocks
    dim3 grid(HH / TILE_H, BB, (COUT / FG) * (CIN / CQ));
    dim3 block(TX, TY, 1);                           // 128 threads
    kaconv_kernel<<<grid, block>>>(x, A, Bc, out);
}